// round 8
// baseline (speedup 1.0000x reference)
#include <cuda_runtime.h>
#include <cuda_fp16.h>

// NeighborhoodAttention 3D, NATTEN clamped window (3,7,7).
// B=1, T=16, H=32, W=32, nh=8, D=128, fp32.
//
// Round 8: fully fused tensor-core kernel, zero smem in main kernel.
//  QK: mma.m16n8k16, exact q hi/lo split (rows 0-7 hi, 8-15 lo) x (khi,klo).
//  PV: mma.m16n8k16, A = [p_hi ; p_lo] (rows free), B = V_hi (f16) -> error
//      only from V f16 rounding ~1.4e-4 << 1e-3.
//  p never touches smem: QK epilogue lane (g,tid4) owns keys 2t4,2t4+1 of
//  each 8-key subchunk == exactly the PV A-fragment slots for row g.
//  Halo = 3 x 8 x 12 (w even-aligned) = 288 keys = 18 chunks of 16; pairs
//  never cross h-lines so V^T half2 pairs (prepass) always line up.

#define T_  16
#define H_  32
#define W_  32
#define NH  8
#define L_  16384
#define QK_SCALE (0.08838834764831845f * 1.4426950408889634f)  // /sqrt(128)*log2e

// K prepass: entry(head, dgrp, l, p) = {khi2(dims 8*dgrp+2p,+1), klo2}
__device__ uint2   g_kp[(size_t)NH * 16 * L_ * 4];          // 64 MB
// V prepass: V^T hi: half2(V[2*l2][d], V[2*l2+1][d]) at [head][d][l2]
__device__ __half2 g_vt[(size_t)NH * 128 * (L_ / 2)];       // 32 MB

__global__ __launch_bounds__(256)
void prep_k(const float* __restrict__ K)
{
    const int tid = blockIdx.x * 256 + threadIdx.x;
    const int l    = tid & (L_ - 1);
    const int hd   = tid >> 14;
    const int head = hd >> 4;
    const int dgrp = hd & 15;
    const float* src = K + ((size_t)l << 10) + (head << 7) + (dgrp << 3);
    const float4 f0 = *(const float4*)(src);
    const float4 f1 = *(const float4*)(src + 4);
    float2 fp[4] = { {f0.x, f0.y}, {f0.z, f0.w}, {f1.x, f1.y}, {f1.z, f1.w} };
    uint2 e[4];
    #pragma unroll
    for (int p = 0; p < 4; ++p) {
        __half2 hi = __float22half2_rn(fp[p]);
        float2 hf = __half22float2(hi);
        __half2 lo = __float22half2_rn(make_float2(fp[p].x - hf.x, fp[p].y - hf.y));
        e[p].x = *(unsigned*)&hi;
        e[p].y = *(unsigned*)&lo;
    }
    uint2* dst = g_kp + (size_t)tid * 4;
    dst[0] = e[0]; dst[1] = e[1]; dst[2] = e[2]; dst[3] = e[3];
}

__global__ __launch_bounds__(256)
void prep_v(const float* __restrict__ V)
{
    // grid 8192: head(8) x dblk(4) x l2blk(256); tile = 32 d x 32 l2 (64 l rows)
    __shared__ float s[64][33];
    const int bx   = blockIdx.x;
    const int head = bx >> 10;
    const int dblk = (bx >> 8) & 3;
    const int l2b  = bx & 255;
    const int lane = threadIdx.x & 31;
    const int wrp  = threadIdx.x >> 5;
    const int lbase = l2b * 64;
    #pragma unroll
    for (int i = 0; i < 8; ++i) {
        const int r = i * 8 + wrp;
        s[r][lane] = V[(size_t)(lbase + r) * 1024 + head * 128 + dblk * 32 + lane];
    }
    __syncthreads();
    #pragma unroll
    for (int i = 0; i < 4; ++i) {
        const int idx = i * 256 + threadIdx.x;
        const int dd = idx >> 5, ll = idx & 31;
        const __half2 hv = __floats2half2_rn(s[2*ll][dd], s[2*ll + 1][dd]);
        g_vt[(size_t)(head * 128 + dblk * 32 + dd) * (L_/2) + l2b * 32 + ll] = hv;
    }
}

static __device__ __forceinline__ void mma16816(
    float& c0, float& c1, float& c2, float& c3,
    unsigned a0, unsigned a1, unsigned a2, unsigned a3,
    unsigned b0, unsigned b1)
{
    asm volatile("mma.sync.aligned.m16n8k16.row.col.f32.f16.f16.f32 "
                 "{%0,%1,%2,%3}, {%4,%5,%6,%7}, {%8,%9}, {%0,%1,%2,%3};"
                 : "+f"(c0), "+f"(c1), "+f"(c2), "+f"(c3)
                 : "r"(a0), "r"(a1), "r"(a2), "r"(a3), "r"(b0), "r"(b1));
}

static __device__ __forceinline__ float ex2f(float x)
{
    float r; asm("ex2.approx.f32 %0, %1;" : "=f"(r) : "f"(x)); return r;
}

__global__ __launch_bounds__(128)
void na3d_fused(const float* __restrict__ Q, float* __restrict__ O)
{
    const int lane = threadIdx.x & 31;
    const int warp = threadIdx.x >> 5;
    const int wg   = blockIdx.x * 4 + warp;

    const int head = wg >> 11;
    const int rem  = wg & 2047;
    const int t    = rem >> 7;
    const int h0   = ((rem >> 3) & 15) * 2;
    const int w0   = (rem & 7) * 4;

    const int st  = min(max(t - 1, 0), T_ - 3);
    const int bh  = min(max(h0 - 3, 0), H_ - 8);
    const int bw  = min(max(w0 - 3, 0), W_ - 10);
    const int bwe = min(bw & ~1, W_ - 12);          // even-aligned 12-wide halo

    const int g    = lane >> 2;
    const int tid4 = lane & 3;
    const int dh = g >> 2, dw = g & 3;
    const int shg = min(max(h0 + dh - 3, 0), H_ - 7);
    const int swg = min(max(w0 + dw - 3, 0), W_ - 7);

    unsigned wmask = 0;
    #pragma unroll
    for (int iw = 0; iw < 12; ++iw) {
        const int kw = bwe + iw;
        if (kw >= swg && kw < swg + 7) wmask |= (1u << iw);
    }

    // ---- QK A fragments: this lane's query row, scaled, hi/lo split ----
    const float* qrow = Q + ((size_t)(t*1024 + (h0+dh)*32 + (w0+dw)) * 1024 + head*128);
    unsigned a0v[8], a1v[8], a2v[8], a3v[8];
    #pragma unroll
    for (int s = 0; s < 8; ++s) {
        const int d0 = s*16 + tid4*2;
        float2 f = *(const float2*)(qrow + d0);
        f.x *= QK_SCALE; f.y *= QK_SCALE;
        __half2 hi = __float22half2_rn(f);
        float2 hf = __half22float2(hi);
        __half2 lo = __float22half2_rn(make_float2(f.x - hf.x, f.y - hf.y));
        a0v[s] = *(unsigned*)&hi; a1v[s] = *(unsigned*)&lo;
        f = *(const float2*)(qrow + d0 + 8);
        f.x *= QK_SCALE; f.y *= QK_SCALE;
        hi = __float22half2_rn(f);
        hf = __half22float2(hi);
        lo = __float22half2_rn(make_float2(f.x - hf.x, f.y - hf.y));
        a2v[s] = *(unsigned*)&hi; a3v[s] = *(unsigned*)&lo;
    }

    const uint2*    kp_head = g_kp + (size_t)(head * 16) * L_ * 4;
    const unsigned* vt_head = (const unsigned*)g_vt + (size_t)head * 128 * (L_/2);
    const unsigned* vt_g    = vt_head + g * (L_/2);       // d = nch*8 + g

    // halo position trackers (advance by 8 keys / 8 pairs, lines: 12 keys, 6 pairs)
    int itL = 0, ihL = 0, iwL = g;          // QK load-key  = sub*8 + g
    int ihE = 0, iwE = 2 * tid4;            // QK epilogue keys = sub*8 + 2t4 (+1)
    int itP0 = 0, ihP0 = 0, ipP0 = tid4;    // PV pair = chunk*8 + tid4
    int itP1 = 0, ihP1 = (tid4 + 4 < 6) ? 0 : 1;
    int ipP1 = (tid4 + 4 < 6) ? (tid4 + 4) : (tid4 - 2);

    float acc[16][4];
    #pragma unroll
    for (int n = 0; n < 16; ++n)
        acc[n][0] = acc[n][1] = acc[n][2] = acc[n][3] = 0.f;
    float lsum = 0.0f;

    #pragma unroll 1
    for (int c = 0; c < 18; ++c) {
        unsigned afr[4];
        #pragma unroll
        for (int sub = 0; sub < 2; ++sub) {
            // ---- QK over 8 keys ----
            const int lL = (st + itL)*1024 + (bh + ihL)*32 + (bwe + iwL);
            const uint2* bp = kp_head + (size_t)lL*4 + tid4;
            float c0 = 0.f, c1 = 0.f, c2 = 0.f, c3 = 0.f;
            #pragma unroll
            for (int s = 0; s < 8; ++s) {
                const uint2 e0 = bp[(size_t)(2*s    ) * (L_*4)];
                const uint2 e1 = bp[(size_t)(2*s + 1) * (L_*4)];
                mma16816(c0,c1,c2,c3, a0v[s],a1v[s],a2v[s],a3v[s], e0.x, e1.x);
                mma16816(c0,c1,c2,c3, a0v[s],a1v[s],a2v[s],a3v[s], e0.y, e1.y);
            }
            const float s0 = c0 + c2;
            const float s1 = c1 + c3;

            const bool vh = (unsigned)(bh + ihE - shg) < 7u;
            const float p0 = (vh && ((wmask >> iwE)       & 1u)) ? ex2f(s0) : 0.0f;
            const float p1 = (vh && ((wmask >> (iwE + 1)) & 1u)) ? ex2f(s1) : 0.0f;
            lsum += p0 + p1;

            const __half h0_ = __float2half_rn(p0);
            const __half h1_ = __float2half_rn(p1);
            const __half l0_ = __float2half_rn(p0 - __half2float(h0_));
            const __half l1_ = __float2half_rn(p1 - __half2float(h1_));
            const __half2 phh = __halves2half2(h0_, h1_);
            const __half2 pll = __halves2half2(l0_, l1_);
            afr[sub*2]     = *(const unsigned*)&phh;   // rows 0-7  (p_hi)
            afr[sub*2 + 1] = *(const unsigned*)&pll;   // rows 8-15 (p_lo)

            // advance trackers by 8 keys
            iwL += 8; if (iwL >= 12) { iwL -= 12; if (++ihL >= 8) { ihL = 0; ++itL; } }
            iwE += 8; if (iwE >= 12) { iwE -= 12; if (++ihE >= 8) { ihE = 0; } }
        }

        // ---- PV over the 16-key chunk ----
        const int l2_0 = (st + itP0)*512 + (bh + ihP0)*16 + (bwe >> 1) + ipP0;
        const int l2_1 = (st + itP1)*512 + (bh + ihP1)*16 + (bwe >> 1) + ipP1;
        #pragma unroll
        for (int n = 0; n < 16; ++n) {
            const unsigned b0 = vt_g[n * 8 * (L_/2) + l2_0];
            const unsigned b1 = vt_g[n * 8 * (L_/2) + l2_1];
            mma16816(acc[n][0], acc[n][1], acc[n][2], acc[n][3],
                     afr[0], afr[1], afr[2], afr[3], b0, b1);
        }

        // advance pair trackers by 8 pairs (lines of 6)
        ipP0 += 8;
        if (ipP0 >= 12) { ipP0 -= 12; ihP0 += 2; } else { ipP0 -= 6; ihP0 += 1; }
        if (ihP0 >= 8) { ihP0 -= 8; ++itP0; }
        ipP1 += 8;
        if (ipP1 >= 12) { ipP1 -= 12; ihP1 += 2; } else { ipP1 -= 6; ihP1 += 1; }
        if (ihP1 >= 8) { ihP1 -= 8; ++itP1; }
    }

    // ---- normalize + store ----
    lsum += __shfl_xor_sync(~0u, lsum, 1);
    lsum += __shfl_xor_sync(~0u, lsum, 2);
    const float inv = 1.0f / lsum;

    float* orow = O + ((size_t)(t*1024 + (h0+dh)*32 + (w0+dw)) * 1024 + head*128);
    #pragma unroll
    for (int n = 0; n < 16; ++n) {
        float2 r;
        r.x = (acc[n][0] + acc[n][2]) * inv;   // row g + row g+8 (p_hi + p_lo)
        r.y = (acc[n][1] + acc[n][3]) * inv;
        *(float2*)(orow + n*8 + 2*tid4) = r;
    }
}

extern "C" void kernel_launch(void* const* d_in, const int* in_sizes, int n_in,
                              void* d_out, int out_size)
{
    const float* q = (const float*)d_in[0];
    const float* k = (const float*)d_in[1];
    const float* v = (const float*)d_in[2];
    float* out = (float*)d_out;

    prep_k<<<(NH * 16 * L_) / 256, 256>>>(k);   // 8192 blocks
    prep_v<<<8192, 256>>>(v);
    na3d_fused<<<4096, 128>>>(q, out);
}

// round 9
// speedup vs baseline: 1.3355x; 1.3355x over previous
#include <cuda_runtime.h>
#include <cuda_fp16.h>

// NeighborhoodAttention 3D, NATTEN clamped window (3,7,7).
// B=1, T=16, H=32, W=32, nh=8, D=128, fp32.
//
// Round 9: R7 structure (QK on tensor cores with exact hi/lo split, max-free
// softmax, p in smem, fp32 PV) with the PV pass rewritten in packed
// fma.rn.f32x2 (FFMA2, 2 fp32 MACs per instruction, sm_103a-only via PTX).
// Accumulators are query-paired: acc[d][{q,q+1}] as b64 -> the p multiplier
// pairs come straight out of smem as LDS.128 (no repacking); only V needs
// 4 splats per key. Per-key PV: 35 inst -> 23.

#define T_  16
#define H_  32
#define W_  32
#define NH  8
#define L_  16384
#define ROW4 256
#define QK_SCALE (0.08838834764831845f * 1.4426950408889634f)  // /sqrt(128)*log2e

// prepass: entry(head, dgrp, l, p) = {khi2(dims 8*dgrp+2p,+1), klo2(same)}
__device__ uint2 g_kp[(size_t)NH * 16 * L_ * 4];   // 64 MB

__global__ __launch_bounds__(256)
void prep_k(const float* __restrict__ K)
{
    const int tid = blockIdx.x * 256 + threadIdx.x;   // 2,097,152 threads
    const int l    = tid & (L_ - 1);
    const int hd   = tid >> 14;            // head*16 + dgrp
    const int head = hd >> 4;
    const int dgrp = hd & 15;
    const float* src = K + ((size_t)l << 10) + (head << 7) + (dgrp << 3);
    const float4 f0 = *(const float4*)(src);
    const float4 f1 = *(const float4*)(src + 4);
    float2 fp[4] = { {f0.x, f0.y}, {f0.z, f0.w}, {f1.x, f1.y}, {f1.z, f1.w} };
    uint2 e[4];
    #pragma unroll
    for (int p = 0; p < 4; ++p) {
        __half2 hi = __float22half2_rn(fp[p]);
        float2 hf = __half22float2(hi);
        __half2 lo = __float22half2_rn(make_float2(fp[p].x - hf.x, fp[p].y - hf.y));
        e[p].x = *(unsigned*)&hi;
        e[p].y = *(unsigned*)&lo;
    }
    uint2* dst = g_kp + (size_t)tid * 4;
    dst[0] = e[0]; dst[1] = e[1]; dst[2] = e[2]; dst[3] = e[3];
}

static __device__ __forceinline__ void mma16816(
    float& c0, float& c1, float& c2, float& c3,
    unsigned a0, unsigned a1, unsigned a2, unsigned a3,
    unsigned b0, unsigned b1)
{
    asm volatile("mma.sync.aligned.m16n8k16.row.col.f32.f16.f16.f32 "
                 "{%0,%1,%2,%3}, {%4,%5,%6,%7}, {%8,%9}, {%0,%1,%2,%3};"
                 : "+f"(c0), "+f"(c1), "+f"(c2), "+f"(c3)
                 : "r"(a0), "r"(a1), "r"(a2), "r"(a3), "r"(b0), "r"(b1));
}

static __device__ __forceinline__ float ex2f(float x)
{
    float r; asm("ex2.approx.f32 %0, %1;" : "=f"(r) : "f"(x)); return r;
}

// packed fp32x2 fma: d = a * b + d   (both halves independent fp32 FMAs)
static __device__ __forceinline__ void fma2(unsigned long long& d,
                                            unsigned long long a,
                                            unsigned long long b)
{
    asm("fma.rn.f32x2 %0, %1, %2, %0;" : "+l"(d) : "l"(a), "l"(b));
}

static __device__ __forceinline__ unsigned long long splat2(float x)
{
    unsigned long long r;
    asm("mov.b64 %0, {%1, %1};" : "=l"(r) : "f"(x));
    return r;
}

static __device__ __forceinline__ float2 unpack2(unsigned long long v)
{
    float2 r;
    asm("mov.b64 {%0, %1}, %2;" : "=f"(r.x), "=f"(r.y) : "l"(v));
    return r;
}

__global__ __launch_bounds__(128)
void na3d_mma(const float* __restrict__ Q,
              const float* __restrict__ V,
              float* __restrict__ O)
{
    __shared__ __align__(16) float s_p[4][240 * 8];    // 30 KB probs

    const int lane = threadIdx.x & 31;
    const int warp = threadIdx.x >> 5;
    const int wg   = blockIdx.x * 4 + warp;

    const int head = wg >> 11;
    const int rem  = wg & 2047;
    const int t    = rem >> 7;
    const int h0   = ((rem >> 3) & 15) * 2;
    const int w0   = (rem & 7) * 4;

    const int st = min(max(t - 1, 0), T_ - 3);
    const int bh = min(max(h0 - 3, 0), H_ - 8);
    const int bw = min(max(w0 - 3, 0), W_ - 10);

    const int g    = lane >> 2;          // query of this lane (epilogue & A rows)
    const int tid4 = lane & 3;
    const int dh = g >> 2, dw = g & 3;
    const int shg = min(max(h0 + dh - 3, 0), H_ - 7);
    const int swg = min(max(w0 + dw - 3, 0), W_ - 7);

    unsigned wmask = 0;
    #pragma unroll
    for (int iw = 0; iw < 10; ++iw) {
        const int kw = bw + iw;
        if (kw >= swg && kw < swg + 7) wmask |= (1u << iw);
    }

    // ---- A fragments: split this lane's query row (scaled) into hi/lo ----
    const float* qrow = Q + ((size_t)(t*1024 + (h0+dh)*32 + (w0+dw)) * 1024 + head*128);
    unsigned a0v[8], a1v[8], a2v[8], a3v[8];
    #pragma unroll
    for (int s = 0; s < 8; ++s) {
        const int d0 = s*16 + tid4*2;
        float2 f = *(const float2*)(qrow + d0);
        f.x *= QK_SCALE; f.y *= QK_SCALE;
        __half2 hi = __float22half2_rn(f);
        float2 hf = __half22float2(hi);
        __half2 lo = __float22half2_rn(make_float2(f.x - hf.x, f.y - hf.y));
        a0v[s] = *(unsigned*)&hi; a1v[s] = *(unsigned*)&lo;
        f = *(const float2*)(qrow + d0 + 8);
        f.x *= QK_SCALE; f.y *= QK_SCALE;
        hi = __float22half2_rn(f);
        hf = __half22float2(hi);
        lo = __float22half2_rn(make_float2(f.x - hf.x, f.y - hf.y));
        a2v[s] = *(unsigned*)&hi; a3v[s] = *(unsigned*)&lo;
    }

    float* sp = s_p[warp];
    const uint2* kp_head = g_kp + (size_t)(head * 16) * L_ * 4;
    const int nK = g;              // B-fragment key this lane loads
    const int eK = tid4 * 2;       // epilogue keys this lane owns

    // ---------------- QK pass: 30 chunks of 8 keys ----------------
    float lsum = 0.0f;
    #pragma unroll 1
    for (int c = 0; c < 30; ++c) {
        const int kL  = c*8 + nK;
        const int itL = kL / 80;  const int rL = kL - itL*80;
        const int ihL = rL / 10;  const int iwL = rL - ihL*10;
        const int lL  = (st+itL)*1024 + (bh+ihL)*32 + (bw+iwL);
        const uint2* bp = kp_head + (size_t)lL*4 + tid4;

        float c0 = 0.f, c1 = 0.f, c2 = 0.f, c3 = 0.f;
        #pragma unroll
        for (int s = 0; s < 8; ++s) {
            const uint2 e0 = bp[(size_t)(2*s    ) * (L_*4)];
            const uint2 e1 = bp[(size_t)(2*s + 1) * (L_*4)];
            mma16816(c0,c1,c2,c3, a0v[s],a1v[s],a2v[s],a3v[s], e0.x, e1.x);  // x khi
            mma16816(c0,c1,c2,c3, a0v[s],a1v[s],a2v[s],a3v[s], e0.y, e1.y);  // x klo
        }
        const float s0 = c0 + c2;   // score(g, key eK)
        const float s1 = c1 + c3;   // score(g, key eK+1)

        const int k0  = c*8 + eK;
        const int it0 = k0 / 80;  const int r0 = k0 - it0*80;
        const int ih0 = r0 / 10;  const int iw0 = r0 - ih0*10;
        const int k1  = k0 + 1;
        const int it1 = k1 / 80;  const int r1 = k1 - it1*80;
        const int ih1 = r1 / 10;  const int iw1 = r1 - ih1*10;
        const bool v0 = ((unsigned)(bh + ih0 - shg) < 7u) && ((wmask >> iw0) & 1u);
        const bool v1 = ((unsigned)(bh + ih1 - shg) < 7u) && ((wmask >> iw1) & 1u);

        const float p0 = v0 ? ex2f(s0) : 0.0f;
        const float p1 = v1 ? ex2f(s1) : 0.0f;
        lsum += p0 + p1;
        sp[k0*8 + g] = p0;
        sp[k1*8 + g] = p1;
    }
    __syncwarp();
    lsum += __shfl_xor_sync(~0u, lsum, 1);
    lsum += __shfl_xor_sync(~0u, lsum, 2);
    const float inv = 1.0f / lsum;          // lanes 4g..4g+3 hold inv(g)

    // ---------------- PV pass: packed f32x2, query-paired accs ----------------
    const float4* __restrict__ V4 = (const float4*)V;
    float4* __restrict__ O4 = (float4*)O;
    const int qbase = (t*1024 + h0*32 + w0) * ROW4 + head*32 + lane;
    const int kbase = (st*1024 + bh*32 + bw) * ROW4 + head*32 + lane;

    // acc[qp][d'] : qp = query pair (q01,q23,q45,q67), d' = lane dim 0..3
    unsigned long long acc[4][4];
    #pragma unroll
    for (int a = 0; a < 4; ++a)
        acc[a][0] = acc[a][1] = acc[a][2] = acc[a][3] = 0ull;

    int ridx8 = 0;
    #pragma unroll 1
    for (int it = 0; it < 3; ++it) {
        #pragma unroll 1
        for (int ih = 0; ih < 8; ++ih) {
            const int rowb = kbase + (it*1024 + ih*32) * ROW4;
            #pragma unroll 5
            for (int iw = 0; iw < 10; ++iw) {
                // p pairs straight from smem: {p0,p1},{p2,p3},{p4,p5},{p6,p7}
                const ulonglong2 pA = *(const ulonglong2*)&sp[ridx8 + iw*8];
                const ulonglong2 pB = *(const ulonglong2*)&sp[ridx8 + iw*8 + 4];
                const float4 vv = V4[rowb + iw * ROW4];
                const unsigned long long vx = splat2(vv.x);
                const unsigned long long vy = splat2(vv.y);
                const unsigned long long vz = splat2(vv.z);
                const unsigned long long vw = splat2(vv.w);
                fma2(acc[0][0], pA.x, vx); fma2(acc[0][1], pA.x, vy);
                fma2(acc[0][2], pA.x, vz); fma2(acc[0][3], pA.x, vw);
                fma2(acc[1][0], pA.y, vx); fma2(acc[1][1], pA.y, vy);
                fma2(acc[1][2], pA.y, vz); fma2(acc[1][3], pA.y, vw);
                fma2(acc[2][0], pB.x, vx); fma2(acc[2][1], pB.x, vy);
                fma2(acc[2][2], pB.x, vz); fma2(acc[2][3], pB.x, vw);
                fma2(acc[3][0], pB.y, vx); fma2(acc[3][1], pB.y, vy);
                fma2(acc[3][2], pB.y, vz); fma2(acc[3][3], pB.y, vw);
            }
            ridx8 += 80;
        }
    }

    // ---------------- scale + store ----------------
    #pragma unroll
    for (int a = 0; a < 4; ++a) {
        const float iA = __shfl_sync(~0u, inv, (2*a)     << 2);  // inv(q = 2a)
        const float iB = __shfl_sync(~0u, inv, (2*a + 1) << 2);  // inv(q = 2a+1)
        const float2 d0 = unpack2(acc[a][0]);
        const float2 d1 = unpack2(acc[a][1]);
        const float2 d2 = unpack2(acc[a][2]);
        const float2 d3 = unpack2(acc[a][3]);
        float4 rA = make_float4(d0.x*iA, d1.x*iA, d2.x*iA, d3.x*iA);  // query 2a
        float4 rB = make_float4(d0.y*iB, d1.y*iB, d2.y*iB, d3.y*iB);  // query 2a+1
        const int jA = 2*a, jB = 2*a + 1;
        O4[qbase + ((jA >> 2)*32 + (jA & 3)) * ROW4] = rA;
        O4[qbase + ((jB >> 2)*32 + (jB & 3)) * ROW4] = rB;
    }
}

extern "C" void kernel_launch(void* const* d_in, const int* in_sizes, int n_in,
                              void* d_out, int out_size)
{
    const float* q = (const float*)d_in[0];
    const float* k = (const float*)d_in[1];
    const float* v = (const float*)d_in[2];
    float* out = (float*)d_out;

    prep_k<<<(NH * 16 * L_) / 256, 256>>>(k);       // 8192 blocks
    na3d_mma<<<4096, 128>>>(q, v, out);
}